// round 6
// baseline (speedup 1.0000x reference)
#include <cuda_runtime.h>
#include <cstdint>

#define NB_EVENT 2000
#define NB_TYPE  10
#define PRED_LEN 1000
#define RBLK     20
#define NBLK     50            // PRED_LEN / RBLK
#define SEQB     512           // tail window; w>=0.5 => older decay underflows to exactly 0 in f32

// ---- cross-kernel scratch ----
__device__ float g_c [PRED_LEN * NB_TYPE];   // c_{t,i}
__device__ float g_h [NBLK * NB_TYPE];       // h_t = u_{t,20}
__device__ float g_S0[NB_TYPE];

// ============================ K1: parallel precompute ============================
// blocks 0..49  : warp 0 runs t-block's 20-step u recurrence in registers
// blocks 50..57 : copy training block to out
// block  58     : S0 reduction
__global__ __launch_bounds__(256, 1)
void k1_kernel(const int* __restrict__ seq_id,
               const float* __restrict__ sequences,
               const float* __restrict__ spontaneous,
               const float* __restrict__ theta,
               const float* __restrict__ w,
               const float* __restrict__ alpha,
               float* __restrict__ out)
{
    const int bid = blockIdx.x;
    const int tid = threadIdx.x;
    const int sid = seq_id[0];
    const float* __restrict__ seq = sequences + (size_t)sid * NB_EVENT * NB_TYPE;

    if (bid < NBLK) {
        if (tid >= 32) return;
        const int  lane = tid;
        const bool act  = (lane < NB_TYPE);
        const int  k    = act ? lane : 0;

        float wk = 1.0f, th = 0.0f, ak = 0.0f, er = 1.0f, ew = 0.0f;
        if (act) {
            wk = w[sid * NB_TYPE + k];
            th = theta[sid * NB_TYPE + k];
            const float sp = spontaneous[sid * NB_TYPE + k];
            ew = expf(-wk);
            er = expf(-th);
            ak = sp / th * (1.0f - er);
        }
        const float som_self = 1.0f - ew;
        const float rwk = 1.0f / wk;
        float Brow[10], Mrow[10];
        #pragma unroll
        for (int m = 0; m < 10; m++) {
            const float som_m = __shfl_sync(0xFFFFFFFFu, som_self, m);
            const float al = act ? alpha[((size_t)sid * NB_TYPE + k) * NB_TYPE + m] : 0.0f;
            Brow[m] = rwk * al * som_m;
            Mrow[m] = ew * ((k == m ? 1.0f : 0.0f) + Brow[m]);
        }

        const int t = bid;
        float v = act ? ak * expf(-th * (float)(NB_EVENT + t * RBLK)) : 0.0f;
        float u = 0.0f;
        #pragma unroll
        for (int i = 0; i < RBLK; i++) {
            const float s0 = __shfl_sync(0xFFFFFFFFu, u, 0);
            const float s1 = __shfl_sync(0xFFFFFFFFu, u, 1);
            const float s2 = __shfl_sync(0xFFFFFFFFu, u, 2);
            const float s3 = __shfl_sync(0xFFFFFFFFu, u, 3);
            const float s4 = __shfl_sync(0xFFFFFFFFu, u, 4);
            const float s5 = __shfl_sync(0xFFFFFFFFu, u, 5);
            const float s6 = __shfl_sync(0xFFFFFFFFu, u, 6);
            const float s7 = __shfl_sync(0xFFFFFFFFu, u, 7);
            const float s8 = __shfl_sync(0xFFFFFFFFu, u, 8);
            const float s9 = __shfl_sync(0xFFFFFFFFu, u, 9);

            float ca = v;
            float ua = ew * v;
            ca += Brow[0]*s0; ua += Mrow[0]*s0;
            ca += Brow[1]*s1; ua += Mrow[1]*s1;
            ca += Brow[2]*s2; ua += Mrow[2]*s2;
            ca += Brow[3]*s3; ua += Mrow[3]*s3;
            ca += Brow[4]*s4; ua += Mrow[4]*s4;
            ca += Brow[5]*s5; ua += Mrow[5]*s5;
            ca += Brow[6]*s6; ua += Mrow[6]*s6;
            ca += Brow[7]*s7; ua += Mrow[7]*s7;
            ca += Brow[8]*s8; ua += Mrow[8]*s8;
            ca += Brow[9]*s9; ua += Mrow[9]*s9;

            if (act) g_c[(t * RBLK + i) * NB_TYPE + k] = ca;
            u = ua;
            v *= er;
        }
        if (act) g_h[t * NB_TYPE + k] = u;

    } else if (bid < 58) {
        const int gtid = (bid - 50) * 256 + tid;
        const float4* __restrict__ s4 = (const float4*)seq;
        float4* __restrict__ o4 = (float4*)out;
        for (int i = gtid; i < (NB_EVENT * NB_TYPE) / 4; i += 2048)
            o4[i] = s4[i];

    } else {
        const int wid = tid >> 5, lane = tid & 31;
        for (int k = wid; k < NB_TYPE; k += 8) {
            const float wk = w[sid * NB_TYPE + k];
            float d = expf(-wk * (float)(1 + lane));
            const float r = expf(-32.0f * wk);
            float acc = 0.0f;
            #pragma unroll
            for (int j = 0; j < SEQB / 32; j++) {
                const int e = (NB_EVENT - 1 - lane) - 32 * j;
                acc += seq[e * NB_TYPE + k] * d;
                d *= r;
            }
            #pragma unroll
            for (int off = 16; off > 0; off >>= 1)
                acc += __shfl_xor_sync(0xFFFFFFFFu, acc, off);
            if (lane == 0) g_S0[k] = acc;
        }
    }
}

// ============================ K2: fused matrices + scan + pred ============================
// warp 0      : private M^20 chain (syncwarp) then 49-iter serial scan -> sSt
// warps 1..25 : prefix-doubling M^1..M^19, then R_i = B*M^i  (named barrier 1, 800 thr)
// join (__syncthreads), then all 1024 threads: pred = c + R_i*S_t -> out
__global__ __launch_bounds__(1024, 1)
void k2_kernel(const int* __restrict__ seq_id,
               const float* __restrict__ w,
               const float* __restrict__ alpha,
               float* __restrict__ out)
{
    __shared__ float sB[100], sM[100];
    __shared__ float sPw[20][100];     // M^i, i=1..19
    __shared__ float sRr[20][100];     // R_0 = B, R_i = B*M^i
    __shared__ float c0[100], c1[100], c2[100], c3[100];   // warp0 chain
    __shared__ float sh[NBLK * NB_TYPE], sSt[NBLK * NB_TYPE];
    __shared__ float sEW[16], sOM[16], sRW[16];

    const int tid  = threadIdx.x;
    const int wid  = tid >> 5;
    const int lane = tid & 31;
    const int sid  = seq_id[0];

    if (tid < NB_TYPE) {
        const float wk = w[sid * NB_TYPE + tid];
        const float e  = expf(-wk);
        sEW[tid] = e; sOM[tid] = 1.0f - e; sRW[tid] = 1.0f / wk;
    }
    __syncthreads();
    if (tid < 100) {
        const int k = tid / 10, j = tid - (tid / 10) * 10;
        const float b = sRW[k] * alpha[((size_t)sid * NB_TYPE + k) * NB_TYPE + j] * sOM[j];
        sB[tid] = b;
        sRr[0][tid] = b;
        const float m = sEW[k] * ((k == j ? 1.0f : 0.0f) + b);
        sM[tid] = m;
        sPw[1][tid] = m;
    }
    __syncthreads();

    if (wid == 0) {
        // stage h and S0
        for (int i = lane; i < NBLK * NB_TYPE; i += 32) sh[i] = g_h[i];
        const float S0v = (lane < NB_TYPE) ? g_S0[lane] : 0.0f;

        // private squaring chain: M2->c0, M4->c1, M8->c0's sib... (no aliasing)
        #define WSQ(D, A, Bm)                                              \
        {                                                                  \
            _Pragma("unroll")                                              \
            for (int q = 0; q < 4; q++) {                                  \
                const int p = lane + 32 * q;                               \
                if (p < 100) {                                             \
                    const int kk = p / 10, jj = p - kk * 10;               \
                    float a = 0.0f;                                        \
                    _Pragma("unroll")                                      \
                    for (int m = 0; m < 10; m++)                           \
                        a += (A)[kk * 10 + m] * (Bm)[m * 10 + jj];         \
                    (D)[p] = a;                                            \
                }                                                          \
            }                                                              \
            __syncwarp();                                                  \
        }
        WSQ(c0, sM, sM);   // M^2
        WSQ(c1, c0, c0);   // M^4
        WSQ(c2, c1, c1);   // M^8
        WSQ(c3, c2, c2);   // M^16
        WSQ(c0, c3, c1);   // M^20  (c0 reused; inputs c3,c1)
        #undef WSQ

        const bool act = (lane < NB_TYPE);
        const int  k   = act ? lane : 0;
        float Pr[10];
        #pragma unroll
        for (int m = 0; m < 10; m++) Pr[m] = c0[k * 10 + m];

        float S = act ? S0v : 0.0f;
        if (act) sSt[k] = S;

        for (int t = 0; t < NBLK - 1; t++) {
            const float s0 = __shfl_sync(0xFFFFFFFFu, S, 0);
            const float s1 = __shfl_sync(0xFFFFFFFFu, S, 1);
            const float s2 = __shfl_sync(0xFFFFFFFFu, S, 2);
            const float s3 = __shfl_sync(0xFFFFFFFFu, S, 3);
            const float s4 = __shfl_sync(0xFFFFFFFFu, S, 4);
            const float s5 = __shfl_sync(0xFFFFFFFFu, S, 5);
            const float s6 = __shfl_sync(0xFFFFFFFFu, S, 6);
            const float s7 = __shfl_sync(0xFFFFFFFFu, S, 7);
            const float s8 = __shfl_sync(0xFFFFFFFFu, S, 8);
            const float s9 = __shfl_sync(0xFFFFFFFFu, S, 9);

            const float p0 = Pr[0]*s0, p1 = Pr[1]*s1, p2 = Pr[2]*s2, p3 = Pr[3]*s3;
            const float p4 = Pr[4]*s4, p5 = Pr[5]*s5, p6 = Pr[6]*s6, p7 = Pr[7]*s7;
            const float p8 = Pr[8]*s8, p9 = Pr[9]*s9;
            const float h  = sh[t * NB_TYPE + k];
            const float q0 = p0+p1, q1 = p2+p3, q2 = p4+p5, q3 = p6+p7, q4 = p8+p9;
            const float r0 = q0+q1, r1 = q2+q3, r2 = q4+h;
            S = (r0 + r1) + r2;
            if (act) sSt[(t + 1) * NB_TYPE + k] = S;
        }
    } else if (wid < 26) {
        // 800 threads; named barrier 1 (count 800), independent of warp 0
        const int r    = tid - 32;
        const int slot = r / 100;
        const int e    = r - slot * 100;
        const int kk   = e / 10, jj = e - kk * 10;

        #define MMUL(D, A, Bm)                                             \
        {                                                                  \
            float a = 0.0f;                                                \
            _Pragma("unroll")                                              \
            for (int m = 0; m < 10; m++)                                   \
                a += (A)[kk * 10 + m] * (Bm)[m * 10 + jj];                 \
            (D)[e] = a;                                                    \
        }
        #define RBAR asm volatile("bar.sync 1, 800;" ::: "memory")

        if (slot == 0) MMUL(sPw[2], sPw[1], sPw[1]);
        RBAR;
        if (slot < 2)  MMUL(sPw[3 + slot], sPw[2], sPw[1 + slot]);
        RBAR;
        if (slot < 4)  MMUL(sPw[5 + slot], sPw[4], sPw[1 + slot]);
        RBAR;
        if (slot < 8)  MMUL(sPw[9 + slot], sPw[8], sPw[1 + slot]);
        RBAR;
        if (slot < 3)  MMUL(sPw[17 + slot], sPw[16], sPw[1 + slot]);
        RBAR;
        if (slot < 8)  MMUL(sRr[1 + slot], sB, sPw[1 + slot]);
        RBAR;
        if (slot < 8)  MMUL(sRr[9 + slot], sB, sPw[9 + slot]);
        RBAR;
        if (slot < 3)  MMUL(sRr[17 + slot], sB, sPw[17 + slot]);
        #undef MMUL
        #undef RBAR
    }
    __syncthreads();

    // ---- pred epilogue: all 1024 threads ----
    for (int idx = tid; idx < PRED_LEN * NB_TYPE; idx += 1024) {
        const int t   = idx / (RBLK * NB_TYPE);
        const int rem = idx - t * (RBLK * NB_TYPE);
        const int i   = rem / NB_TYPE;
        const int k   = rem - i * NB_TYPE;
        float acc = g_c[idx];
        #pragma unroll
        for (int m = 0; m < 10; m++)
            acc += sRr[i][k * 10 + m] * sSt[t * NB_TYPE + m];
        out[NB_EVENT * NB_TYPE + idx] = acc;
    }
}

extern "C" void kernel_launch(void* const* d_in, const int* in_sizes, int n_in,
                              void* d_out, int out_size)
{
    const int*   seq_id      = (const int*)  d_in[0];
    const float* sequences   = (const float*)d_in[1];
    const float* spontaneous = (const float*)d_in[2];
    const float* theta       = (const float*)d_in[3];
    const float* w           = (const float*)d_in[4];
    const float* alpha       = (const float*)d_in[5];
    float* out = (float*)d_out;

    k1_kernel<<<59, 256>>>(seq_id, sequences, spontaneous, theta, w, alpha, out);
    k2_kernel<<<1, 1024>>>(seq_id, w, alpha, out);
}

// round 7
// speedup vs baseline: 1.0135x; 1.0135x over previous
#include <cuda_runtime.h>
#include <cstdint>

#define NB_EVENT 2000
#define NB_TYPE  10
#define PRED_LEN 1000
#define RBLK     20
#define NBLK     50           // PRED_LEN / RBLK
#define SEQB     512          // tail window; w>=0.5 => older decay underflows to exactly 0 in f32
#define CREW     704          // warps 0..21

__global__ __launch_bounds__(1024, 1)
void hawkes_one(const int* __restrict__ seq_id,
                const float* __restrict__ sequences,
                const float* __restrict__ spontaneous,
                const float* __restrict__ theta,
                const float* __restrict__ w,
                const float* __restrict__ alpha,
                float* __restrict__ out)
{
    __shared__ float sPw[21][100];          // M^0..M^20 (Pw[0]=I)
    __shared__ float sK [21][100];          // K_1..K_20
    __shared__ float sG [20][100];          // G_0..G_19 (G_0=0)
    __shared__ float sR [20][100];          // R_0..R_19 (R_0=B)
    __shared__ float sB [100];
    __shared__ float fv20[NBLK * NB_TYPE];  // f at block starts
    __shared__ float sh  [NBLK * NB_TYPE];  // h_t
    __shared__ float sSt [NBLK * NB_TYPE];  // S_t
    __shared__ float erp [RBLK][NB_TYPE];   // exp(-theta_k * i)
    __shared__ float sEW[10], sOM[10], sRW[10], sTH[10], sAK[10];
    __shared__ float sS0[10];

    const int tid  = threadIdx.x;
    const int wid  = tid >> 5;
    const int lane = tid & 31;

    const int sid = seq_id[0];
    const float* __restrict__ seq = sequences + (size_t)sid * NB_EVENT * NB_TYPE;

    if (wid >= 22) {
        // ================= S0 + train copy (never touches barrier 1) =================
        const int k = wid - 22;                          // 0..9
        const float wk = w[sid * NB_TYPE + k];
        float d = expf(-wk * (float)(1 + lane));         // decay at e = 1999 - lane
        const float r = expf(-32.0f * wk);
        float acc = 0.0f;
        #pragma unroll
        for (int j = 0; j < SEQB / 32; j++) {
            const int e = (NB_EVENT - 1 - lane) - 32 * j;
            acc += seq[e * NB_TYPE + k] * d;
            d *= r;
        }
        #pragma unroll
        for (int off = 16; off > 0; off >>= 1)
            acc += __shfl_xor_sync(0xFFFFFFFFu, acc, off);
        if (lane == 0) sS0[k] = acc;

        // copy 20000 floats = 5000 float4 across 320 threads
        const int ct = (wid - 22) * 32 + lane;
        const float4* __restrict__ s4 = (const float4*)seq;
        float4* __restrict__ o4 = (float4*)out;
        #pragma unroll
        for (int i = ct; i < (NB_EVENT * NB_TYPE) / 4; i += 320)
            o4[i] = s4[i];
    } else {
        // ================= matrix crew: 704 threads, named barrier rounds ============
        #define CBAR asm volatile("bar.sync 1, %0;" :: "n"(CREW) : "memory")
        #define MM(D, A, Bm, e)                                            \
        {                                                                  \
            const int kk = (e) / 10, jj = (e) - kk * 10;                   \
            float a = 0.0f;                                                \
            _Pragma("unroll")                                              \
            for (int m = 0; m < 10; m++)                                   \
                a += (A)[kk * 10 + m] * (Bm)[m * 10 + jj];                 \
            (D)[e] = a;                                                    \
        }

        // r0: per-type params
        if (tid < NB_TYPE) {
            const float wk = w[sid * NB_TYPE + tid];
            const float th = theta[sid * NB_TYPE + tid];
            const float sp = spontaneous[sid * NB_TYPE + tid];
            const float e  = expf(-wk);
            sEW[tid] = e;
            sOM[tid] = 1.0f - e;
            sRW[tid] = 1.0f / wk;
            sTH[tid] = th;
            sAK[tid] = sp / th * (1.0f - expf(-th));
        }
        CBAR;
        // r1: B (=R_0), M (=Pw[1]), Pw[0]=I, erp
        if (tid < 100) {
            const int k = tid / 10, j = tid - (tid / 10) * 10;
            const float b = sRW[k] * alpha[((size_t)sid * NB_TYPE + k) * NB_TYPE + j] * sOM[j];
            sB[tid] = b;
            sR[0][tid] = b;
            sG[0][tid] = 0.0f;
            sPw[1][tid] = sEW[k] * ((k == j ? 1.0f : 0.0f) + b);
            sPw[0][tid] = (k == j) ? 1.0f : 0.0f;
        } else if (tid < 300) {
            const int e = tid - 100;            // 0..199
            const int i = e / 10, k = e - (e / 10) * 10;
            erp[i][k] = expf(-sTH[k] * (float)i);
        }
        CBAR;
        // r2: M^2 + fv20
        if (tid < 100) { MM(sPw[2], sPw[1], sPw[1], tid); }
        else if (tid < 600) {
            const int e = tid - 100;            // 0..499
            const int t = e / 10, m = e - (e / 10) * 10;
            fv20[e] = sAK[m] * expf(-sTH[m] * (float)(NB_EVENT + RBLK * t));
        }
        CBAR;
        // r3: M^3, M^4
        if (tid < 200) { const int s = tid / 100, e = tid - s * 100; MM(sPw[3 + s], sPw[2], sPw[1 + s], e); }
        CBAR;
        // r4: M^5..M^8
        if (tid < 400) { const int s = tid / 100, e = tid - s * 100; MM(sPw[5 + s], sPw[4], sPw[1 + s], e); }
        CBAR;
        // r5: M^9..M^14
        if (tid < 600) { const int s = tid / 100, e = tid - s * 100; MM(sPw[9 + s], sPw[8], sPw[1 + s], e); }
        CBAR;
        // r6: M^15..M^20
        if (tid < 600) { const int s = tid / 100, e = tid - s * 100; MM(sPw[15 + s], sPw[8], sPw[7 + s], e); }
        CBAR;
        // r7: K_i = sum_{j<i} M^{i-1-j} D^j,  i = 1..20 (2000 entries)
        for (int x = tid; x < 2000; x += CREW) {
            const int i = x / 100 + 1;
            const int e = x - (x / 100) * 100;
            const int k = e / 10, m = e - (e / 10) * 10;
            float a = 0.0f;
            for (int j = 0; j < i; j++)
                a += sPw[i - 1 - j][k * 10 + m] * erp[j][m];
            sK[i][e] = a;
        }
        CBAR;
        // r8: G_i = B*K_i*diag(ew) (i=1..19), R_i = B*M^i (i=1..19)
        for (int x = tid; x < 3800; x += CREW) {
            if (x < 1900) {
                const int i = x / 100 + 1;
                const int e = x - (x / 100) * 100;
                const int k = e / 10, m = e - (e / 10) * 10;
                float a = 0.0f;
                #pragma unroll
                for (int n = 0; n < 10; n++)
                    a += sB[k * 10 + n] * sK[i][n * 10 + m];
                sG[i][e] = a * sEW[m];
            } else {
                const int y = x - 1900;
                const int i = y / 100 + 1;
                const int e = y - (y / 100) * 100;
                MM(sR[i], sB, sPw[i], e);
            }
        }
        CBAR;
        // r9: h_t = K_20 * diag(ew) * fv20_t
        if (tid < NBLK * NB_TYPE) {
            const int t = tid / 10, k = tid - (tid / 10) * 10;
            float a = 0.0f;
            #pragma unroll
            for (int m = 0; m < 10; m++)
                a += sK[20][k * 10 + m] * sEW[m] * fv20[t * 10 + m];
            sh[tid] = a;
        }
        #undef MM
        #undef CBAR
    }
    __syncthreads();

    // ================= serial scan: warp 0, 49 iterations =================
    if (wid == 0) {
        const bool act = (lane < NB_TYPE);
        const int  k   = act ? lane : 0;
        float Pr[10];
        #pragma unroll
        for (int m = 0; m < 10; m++) Pr[m] = sPw[20][k * 10 + m];

        float S = act ? sS0[k] : 0.0f;
        if (act) sSt[k] = S;

        for (int t = 0; t < NBLK - 1; t++) {
            const float s0 = __shfl_sync(0xFFFFFFFFu, S, 0);
            const float s1 = __shfl_sync(0xFFFFFFFFu, S, 1);
            const float s2 = __shfl_sync(0xFFFFFFFFu, S, 2);
            const float s3 = __shfl_sync(0xFFFFFFFFu, S, 3);
            const float s4 = __shfl_sync(0xFFFFFFFFu, S, 4);
            const float s5 = __shfl_sync(0xFFFFFFFFu, S, 5);
            const float s6 = __shfl_sync(0xFFFFFFFFu, S, 6);
            const float s7 = __shfl_sync(0xFFFFFFFFu, S, 7);
            const float s8 = __shfl_sync(0xFFFFFFFFu, S, 8);
            const float s9 = __shfl_sync(0xFFFFFFFFu, S, 9);

            const float p0 = Pr[0]*s0, p1 = Pr[1]*s1, p2 = Pr[2]*s2, p3 = Pr[3]*s3;
            const float p4 = Pr[4]*s4, p5 = Pr[5]*s5, p6 = Pr[6]*s6, p7 = Pr[7]*s7;
            const float p8 = Pr[8]*s8, p9 = Pr[9]*s9;
            const float h  = sh[t * NB_TYPE + k];
            const float q0 = p0+p1, q1 = p2+p3, q2 = p4+p5, q3 = p6+p7, q4 = p8+p9;
            const float r0 = q0+q1, r1 = q2+q3, r2 = q4+h;
            S = (r0 + r1) + r2;
            if (act) sSt[(t + 1) * NB_TYPE + k] = S;
        }
    }
    __syncthreads();

    // ================= pred epilogue: all 1024 threads =================
    for (int idx = tid; idx < PRED_LEN * NB_TYPE; idx += 1024) {
        const int t   = idx / (RBLK * NB_TYPE);
        const int rem = idx - t * (RBLK * NB_TYPE);
        const int i   = rem / NB_TYPE;
        const int k   = rem - i * NB_TYPE;
        float acc = erp[i][k] * fv20[t * NB_TYPE + k];
        #pragma unroll
        for (int m = 0; m < 10; m++)
            acc += sG[i][k * 10 + m] * fv20[t * NB_TYPE + m];
        #pragma unroll
        for (int m = 0; m < 10; m++)
            acc += sR[i][k * 10 + m] * sSt[t * NB_TYPE + m];
        out[NB_EVENT * NB_TYPE + idx] = acc;
    }
}

extern "C" void kernel_launch(void* const* d_in, const int* in_sizes, int n_in,
                              void* d_out, int out_size)
{
    const int*   seq_id      = (const int*)  d_in[0];
    const float* sequences   = (const float*)d_in[1];
    const float* spontaneous = (const float*)d_in[2];
    const float* theta       = (const float*)d_in[3];
    const float* w           = (const float*)d_in[4];
    const float* alpha       = (const float*)d_in[5];
    float* out = (float*)d_out;

    hawkes_one<<<1, 1024>>>(seq_id, sequences, spontaneous, theta, w, alpha, out);
}